// round 8
// baseline (speedup 1.0000x reference)
#include <cuda_runtime.h>

// ---------------------------------------------------------------------------
// NLIF recurrent spiking net — persistent kernel.
// Round 8: R6 compute core (scalar FMA, 3/4 weight chunks in regs) +
// butterfly multi-column reduce (70 -> 16 SHFL/warp), acquire-poll,
// per-lane release (closes cross-lane ordering race).
// ---------------------------------------------------------------------------

#define NN 2048
#define TT 2048
#define G  147           // CTAs, 1 per SM (all co-resident on 148 SMs)
#define CPT 14           // columns per CTA (147*14 = 2058 >= 2048)
#define NTHREADS 256
#define NWARPS 8
#define CSTRF 4096       // floats per column slab: 2048 rows x (ws,wf)

#define SMEM_BYTES ((CPT * CSTRF + 16 * NWARPS) * 4)

// persistent device state (no allocations allowed)
__device__ __align__(16) float2 g_state[2][NN];   // (s, s_fast), double-buffered
__device__ unsigned g_cnt[TT + 2];                // per-step counters + epoch slot
__device__ float g_part[TT * G * 2];              // per-CTA readout partials

__device__ __forceinline__ unsigned ld_relaxed_u32(const unsigned* p) {
    unsigned v;
    asm volatile("ld.relaxed.gpu.global.u32 %0, [%1];" : "=r"(v) : "l"(p));
    return v;
}
__device__ __forceinline__ unsigned ld_acquire_u32(const unsigned* p) {
    unsigned v;
    asm volatile("ld.acquire.gpu.global.u32 %0, [%1];" : "=r"(v) : "l"(p));
    return v;
}
__device__ __forceinline__ void red_release_add(unsigned* p, unsigned v) {
    asm volatile("red.release.gpu.global.add.u32 [%0], %1;" :: "l"(p), "r"(v) : "memory");
}

__global__ void __launch_bounds__(NTHREADS, 1)
nlif_kernel(const float* __restrict__ x_in,    // [T][2]
            const float* __restrict__ W_syn,   // [N][N]
            const float* __restrict__ W_fast,  // [N][N]
            const float* __restrict__ W_in,    // [2][N]
            const float* __restrict__ I_o,     // [N]
            const float* __restrict__ O,       // [2][N]
            float* __restrict__ out_spikes,    // [T][N]
            float* __restrict__ out_vs)        // [T][N]
{
    extern __shared__ float smem[];
    float* Wc  = smem;                    // [CPT][CSTRF] : per pair p, (ws0,wf0,ws1,wf1)
    float* red = smem + CPT * CSTRF;      // [16][NWARPS]

    const int tid  = threadIdx.x;
    const int warp = tid >> 5;
    const int lane = tid & 31;
    const int b    = blockIdx.x;
    const int j0   = b * CPT;

    // epoch base: every launch adds exactly 14*G to each counter and to the
    // epoch slot TT+1, which is only bumped after all step-waits complete.
    const unsigned base = ld_relaxed_u32(&g_cnt[TT + 1]);
    const unsigned tgt0 = base + 14u * (unsigned)G;

    // ---- stage weight columns into SMEM, interleaved (ws,wf) per row ----
    for (int i = warp; i < NN; i += NWARPS) {
        if (lane < CPT) {
            const int jj = j0 + lane;
            float ws = 0.f, wf = 0.f;
            if (jj < NN) {
                ws = W_syn[(size_t)i * NN + jj];
                wf = W_fast[(size_t)i * NN + jj];
                if (i == jj) ws = 0.f;              // self-recurrence mask
            }
            const int p = i >> 1, r = i & 1;
            Wc[lane * CSTRF + p * 4 + r * 2 + 0] = ws;
            Wc[lane * CSTRF + p * 4 + r * 2 + 1] = wf;
        }
    }
    __syncthreads();

    // ---- pull k=1,2,3 weight chunks into registers (168 regs/thread) ----
    float4 wr[CPT][3];
    #pragma unroll
    for (int c = 0; c < CPT; c++) {
        #pragma unroll
        for (int kk = 0; kk < 3; kk++) {
            const int p = (kk + 1) * NTHREADS + tid;
            wr[c][kk] = *reinterpret_cast<const float4*>(&Wc[c * CSTRF + p * 4]);
        }
    }

    // ---- per-column persistent state in warp-0 registers ----
    const int j = j0 + lane;
    const bool active = (warp == 0) && (lane < CPT) && (j < NN);
    float v = 0.f, s = 0.f;
    float wi0 = 0.f, wi1 = 0.f, io = 0.f, o0 = 0.f, o1 = 0.f;
    if (active) {
        wi0 = W_in[j];
        wi1 = W_in[NN + j];
        io  = I_o[j];
        o0  = O[j];
        o1  = O[NN + j];
        __stcg(&g_state[0][j], make_float2(0.f, 0.f));   // t=0 reads parity-0 zeros
    }
    if (warp == 0 && lane < CPT) red_release_add(&g_cnt[0], 1u);  // initial publish

    // butterfly result: lane holds column (lane>>1)&15 (two lanes per column)
    const int mycol = (lane >> 1) & 15;

    for (int t = 0; t < TT; t++) {
        const int rb = t & 1;
        const int wb = rb ^ 1;

        float x0 = 0.f, x1 = 0.f;
        if (warp == 0) {
            x0 = __ldg(&x_in[2 * t]);            // prefetch input before the wait
            x1 = __ldg(&x_in[2 * t + 1]);
            // acquire-poll: discovery load doubles as the ordering load
            const unsigned* cp = &g_cnt[t];
            unsigned f = ld_acquire_u32(cp);
            while ((int)(f - tgt0) < 0) {
                f = ld_acquire_u32(cp);
            }
        }
        __syncthreads();

        // ---- load state: 4 coalesced float4 (rows 2p, 2p+1 per float4) ----
        const float2* srow = g_state[rb];
        float4 st[4];
        #pragma unroll
        for (int k = 0; k < 4; k++) {
            const int p = k * NTHREADS + tid;
            st[k] = __ldcg(reinterpret_cast<const float4*>(&srow[2 * p]));
        }

        // ---- dot products: k=0 from SMEM (conflict-free LDS.128), k=1,2,3 from regs ----
        float acc[16];
        #pragma unroll
        for (int c = 0; c < CPT; c++) {
            float a = 0.f;
            {
                const float4 w = *reinterpret_cast<const float4*>(&Wc[c * CSTRF + tid * 4]);
                a = fmaf(st[0].x, w.x, a);
                a = fmaf(st[0].y, w.y, a);
                a = fmaf(st[0].z, w.z, a);
                a = fmaf(st[0].w, w.w, a);
            }
            #pragma unroll
            for (int kk = 0; kk < 3; kk++) {
                const float4 w = wr[c][kk];
                const float4 sv = st[kk + 1];
                a = fmaf(sv.x, w.x, a);
                a = fmaf(sv.y, w.y, a);
                a = fmaf(sv.z, w.z, a);
                a = fmaf(sv.w, w.w, a);
            }
            acc[c] = a;
        }
        acc[14] = 0.f;
        acc[15] = 0.f;

        // ---- butterfly multi-column reduce: 16 SHFL + 16 FADD per warp ----
        // level m: lanes with (lane&m) keep the upper half of their column set.
        #pragma unroll
        for (int i = 0; i < 8; i++) {
            const float give = (lane & 16) ? acc[i] : acc[i + 8];
            const float got  = __shfl_xor_sync(0xffffffffu, give, 16);
            const float keep = (lane & 16) ? acc[i + 8] : acc[i];
            acc[i] = keep + got;
        }
        #pragma unroll
        for (int i = 0; i < 4; i++) {
            const float give = (lane & 8) ? acc[i] : acc[i + 4];
            const float got  = __shfl_xor_sync(0xffffffffu, give, 8);
            const float keep = (lane & 8) ? acc[i + 4] : acc[i];
            acc[i] = keep + got;
        }
        #pragma unroll
        for (int i = 0; i < 2; i++) {
            const float give = (lane & 4) ? acc[i] : acc[i + 2];
            const float got  = __shfl_xor_sync(0xffffffffu, give, 4);
            const float keep = (lane & 4) ? acc[i + 2] : acc[i];
            acc[i] = keep + got;
        }
        {
            const float give = (lane & 2) ? acc[0] : acc[1];
            const float got  = __shfl_xor_sync(0xffffffffu, give, 2);
            const float keep = (lane & 2) ? acc[1] : acc[0];
            acc[0] = keep + got;
        }
        acc[0] += __shfl_xor_sync(0xffffffffu, acc[0], 1);

        if ((lane & 1) == 0) red[mycol * NWARPS + warp] = acc[0];
        __syncthreads();

        if (warp == 0) {
            float r0 = 0.f, r1 = 0.f;
            float s_new = 0.f, gd = 0.f, spk = 0.f, v_new = 0.f;
            if (active) {
                const float4 p0 = *reinterpret_cast<const float4*>(&red[lane * NWARPS]);
                const float4 p1 = *reinterpret_cast<const float4*>(&red[lane * NWARPS + 4]);
                const float sum = ((p0.x + p0.y) + (p0.z + p0.w)) +
                                  ((p1.x + p1.y) + (p1.z + p1.w));

                const float I_tot  = sum + x0 * wi0 + x1 * wi1 + io;
                const float dv     = (I_tot - v) / 10.0f;          // TAU_M
                const float v_next = v + dv;
                const float gating = fminf(fmaxf(v_next, -1.f), 1.f);
                const float dvc    = fminf(fmaxf(dv, -1.f), 1.f);
                gd                 = gating * dvc;
                s_new              = s + (gd - s) / 10.0f;         // TAU_S
                spk                = (v_next >=  1.f) ? 1.f : 0.f;
                const float sn     = (v_next <= -1.f) ? 1.f : 0.f;
                v_new              = (1.f + spk - sn) * v_next;    // matches reference exactly

                v = v_new; s = s_new;
                __stcg(&g_state[wb][j], make_float2(s_new, gd));
            }
            // per-lane release: each lane's RED orders its OWN state store.
            // lanes 0..13 always release (inactive lanes have nothing to order).
            if (lane < CPT) red_release_add(&g_cnt[t + 1], 1u);

            // non-critical outputs after the release
            if (active) {
                out_spikes[(size_t)t * NN + j] = spk;
                out_vs[(size_t)t * NN + j]     = v_new;
                r0 = o0 * s_new;
                r1 = o1 * s_new;
            }
            #pragma unroll
            for (int o = 16; o; o >>= 1) {
                r0 += __shfl_down_sync(0xffffffffu, r0, o);
                r1 += __shfl_down_sync(0xffffffffu, r1, o);
            }
            if (lane == 0) {
                g_part[((size_t)t * G + b) * 2 + 0] = r0;
                g_part[((size_t)t * G + b) * 2 + 1] = r1;
            }
        }
    }

    // bump the epoch slot by 14 per CTA per replay (matches step counters)
    if (warp == 0 && lane < CPT) red_release_add(&g_cnt[TT + 1], 1u);
}

// epilogue: one warp per timestep, coalesced float2 loads + shfl reduce
__global__ void readout_kernel(float* __restrict__ out_ro) {
    const int t    = blockIdx.x * (blockDim.x >> 5) + (threadIdx.x >> 5);
    const int lane = threadIdx.x & 31;
    if (t < TT) {
        const float2* p = reinterpret_cast<const float2*>(&g_part[(size_t)t * G * 2]);
        float a = 0.f, c = 0.f;
        for (int bb = lane; bb < G; bb += 32) {
            const float2 pv = p[bb];
            a += pv.x;
            c += pv.y;
        }
        #pragma unroll
        for (int o = 16; o; o >>= 1) {
            a += __shfl_down_sync(0xffffffffu, a, o);
            c += __shfl_down_sync(0xffffffffu, c, o);
        }
        if (lane == 0) {
            out_ro[2 * t]     = a;
            out_ro[2 * t + 1] = c;
        }
    }
}

extern "C" void kernel_launch(void* const* d_in, const int* in_sizes, int n_in,
                              void* d_out, int out_size) {
    const float* x_in   = (const float*)d_in[0];
    const float* W_syn  = (const float*)d_in[1];
    const float* W_fast = (const float*)d_in[2];
    const float* W_in   = (const float*)d_in[3];
    const float* I_o    = (const float*)d_in[4];
    const float* O      = (const float*)d_in[5];

    float* out        = (float*)d_out;
    float* out_spikes = out;                                // [T][N]
    float* out_ro     = out + (size_t)TT * NN;              // [T][2]
    float* out_vs     = out + (size_t)TT * NN + 2 * TT;     // [T][N]

    cudaFuncSetAttribute(nlif_kernel,
                         cudaFuncAttributeMaxDynamicSharedMemorySize, SMEM_BYTES);

    nlif_kernel<<<G, NTHREADS, SMEM_BYTES>>>(x_in, W_syn, W_fast, W_in, I_o, O,
                                             out_spikes, out_vs);
    // 8 warps per block, one warp per timestep
    readout_kernel<<<TT / 8, NTHREADS>>>(out_ro);
}

// round 9
// speedup vs baseline: 1.6035x; 1.6035x over previous
#include <cuda_runtime.h>

// ---------------------------------------------------------------------------
// NLIF recurrent spiking net — persistent kernel.
// Round 9: R6 core (scalar FMA, 3/4 weight chunks in regs, classic reduce,
// single-lane release) with ONE change: relaxed hot-spin poll, no separate
// acquire confirm round trip (ordering by in-order issue + release-RED + L2).
// ---------------------------------------------------------------------------

#define NN 2048
#define TT 2048
#define G  147           // CTAs, 1 per SM (all co-resident on 148 SMs)
#define CPT 14           // columns per CTA (147*14 = 2058 >= 2048)
#define NTHREADS 256
#define NWARPS 8
#define CSTRF 4096       // floats per column slab: 2048 rows x (ws,wf)

#define SMEM_BYTES ((CPT * CSTRF + CPT * NWARPS) * 4)

// persistent device state (no allocations allowed)
__device__ __align__(16) float2 g_state[2][NN];   // (s, s_fast), double-buffered
__device__ unsigned g_cnt[TT + 2];                // per-step counters + epoch slot
__device__ float g_part[TT * G * 2];              // per-CTA readout partials

__device__ __forceinline__ unsigned ld_relaxed_u32(const unsigned* p) {
    unsigned v;
    asm volatile("ld.relaxed.gpu.global.u32 %0, [%1];" : "=r"(v) : "l"(p) : "memory");
    return v;
}
__device__ __forceinline__ void red_release_add(unsigned* p, unsigned v) {
    asm volatile("red.release.gpu.global.add.u32 [%0], %1;" :: "l"(p), "r"(v) : "memory");
}

__global__ void __launch_bounds__(NTHREADS, 1)
nlif_kernel(const float* __restrict__ x_in,    // [T][2]
            const float* __restrict__ W_syn,   // [N][N]
            const float* __restrict__ W_fast,  // [N][N]
            const float* __restrict__ W_in,    // [2][N]
            const float* __restrict__ I_o,     // [N]
            const float* __restrict__ O,       // [2][N]
            float* __restrict__ out_spikes,    // [T][N]
            float* __restrict__ out_vs)        // [T][N]
{
    extern __shared__ float smem[];
    float* Wc  = smem;                    // [CPT][CSTRF] : per pair p, (ws0,wf0,ws1,wf1)
    float* red = smem + CPT * CSTRF;      // [CPT][NWARPS]

    const int tid  = threadIdx.x;
    const int warp = tid >> 5;
    const int lane = tid & 31;
    const int b    = blockIdx.x;
    const int j0   = b * CPT;

    // epoch base: all counters equal R*G at launch start; slot TT+1 is bumped
    // once per CTA at kernel end, so it reads exactly R*G here.
    const unsigned base = ld_relaxed_u32(&g_cnt[TT + 1]);
    const unsigned tgt0 = base + (unsigned)G;

    // ---- stage weight columns into SMEM, interleaved (ws,wf) per row ----
    for (int i = warp; i < NN; i += NWARPS) {
        if (lane < CPT) {
            const int jj = j0 + lane;
            float ws = 0.f, wf = 0.f;
            if (jj < NN) {
                ws = W_syn[(size_t)i * NN + jj];
                wf = W_fast[(size_t)i * NN + jj];
                if (i == jj) ws = 0.f;              // self-recurrence mask
            }
            const int p = i >> 1, r = i & 1;
            Wc[lane * CSTRF + p * 4 + r * 2 + 0] = ws;
            Wc[lane * CSTRF + p * 4 + r * 2 + 1] = wf;
        }
    }
    __syncthreads();

    // ---- pull k=1,2,3 weight chunks into registers (168 regs/thread) ----
    float4 wr[CPT][3];
    #pragma unroll
    for (int c = 0; c < CPT; c++) {
        #pragma unroll
        for (int kk = 0; kk < 3; kk++) {
            const int p = (kk + 1) * NTHREADS + tid;
            wr[c][kk] = *reinterpret_cast<const float4*>(&Wc[c * CSTRF + p * 4]);
        }
    }

    // ---- per-column persistent state in warp-0 registers ----
    const int j = j0 + lane;
    const bool active = (warp == 0) && (lane < CPT) && (j < NN);
    float v = 0.f, s = 0.f;
    float wi0 = 0.f, wi1 = 0.f, io = 0.f, o0 = 0.f, o1 = 0.f;
    if (active) {
        wi0 = W_in[j];
        wi1 = W_in[NN + j];
        io  = I_o[j];
        o0  = O[j];
        o1  = O[NN + j];
        __stcg(&g_state[0][j], make_float2(0.f, 0.f));   // t=0 reads parity-0 zeros
    }
    if (warp == 0 && lane == 0) red_release_add(&g_cnt[0], 1u);  // initial publish

    for (int t = 0; t < TT; t++) {
        const int rb = t & 1;
        const int wb = rb ^ 1;

        float x0 = 0.f, x1 = 0.f;
        if (warp == 0) {
            x0 = __ldg(&x_in[2 * t]);            // prefetch input before the wait
            x1 = __ldg(&x_in[2 * t + 1]);
            // relaxed hot-spin. No acquire confirm: in-order issue + the
            // producer's release-RED (state committed to L2 before flag is
            // visible) + ldcg-to-L2 state reads make the later loads safe.
            const unsigned* cp = &g_cnt[t];
            unsigned f = ld_relaxed_u32(cp);
            while ((int)(f - tgt0) < 0) {
                f = ld_relaxed_u32(cp);
            }
        }
        __syncthreads();

        // ---- load state: 4 coalesced float4 (rows 2p, 2p+1 per float4) ----
        const float2* srow = g_state[rb];
        float4 st[4];
        #pragma unroll
        for (int k = 0; k < 4; k++) {
            const int p = k * NTHREADS + tid;
            st[k] = __ldcg(reinterpret_cast<const float4*>(&srow[2 * p]));
        }

        // ---- dot products: k=0 from SMEM (conflict-free LDS.128), k=1,2,3 from regs ----
        float acc[CPT];
        #pragma unroll
        for (int c = 0; c < CPT; c++) {
            float a = 0.f;
            {
                const float4 w = *reinterpret_cast<const float4*>(&Wc[c * CSTRF + tid * 4]);
                a = fmaf(st[0].x, w.x, a);
                a = fmaf(st[0].y, w.y, a);
                a = fmaf(st[0].z, w.z, a);
                a = fmaf(st[0].w, w.w, a);
            }
            #pragma unroll
            for (int kk = 0; kk < 3; kk++) {
                const float4 w = wr[c][kk];
                const float4 sv = st[kk + 1];
                a = fmaf(sv.x, w.x, a);
                a = fmaf(sv.y, w.y, a);
                a = fmaf(sv.z, w.z, a);
                a = fmaf(sv.w, w.w, a);
            }
            acc[c] = a;
        }

        // ---- intra-warp tree reduce, stash per-warp partials ----
        #pragma unroll
        for (int c = 0; c < CPT; c++) {
            float x = acc[c];
            x += __shfl_down_sync(0xffffffffu, x, 16);
            x += __shfl_down_sync(0xffffffffu, x, 8);
            x += __shfl_down_sync(0xffffffffu, x, 4);
            x += __shfl_down_sync(0xffffffffu, x, 2);
            x += __shfl_down_sync(0xffffffffu, x, 1);
            if (lane == 0) red[c * NWARPS + warp] = x;
        }
        __syncthreads();

        if (warp == 0) {
            float r0 = 0.f, r1 = 0.f;
            float s_new = 0.f, gd = 0.f, spk = 0.f, v_new = 0.f;
            if (active) {
                const float4 p0 = *reinterpret_cast<const float4*>(&red[lane * NWARPS]);
                const float4 p1 = *reinterpret_cast<const float4*>(&red[lane * NWARPS + 4]);
                const float sum = ((p0.x + p0.y) + (p0.z + p0.w)) +
                                  ((p1.x + p1.y) + (p1.z + p1.w));

                const float I_tot  = sum + x0 * wi0 + x1 * wi1 + io;
                const float dv     = (I_tot - v) / 10.0f;          // TAU_M
                const float v_next = v + dv;
                const float gating = fminf(fmaxf(v_next, -1.f), 1.f);
                const float dvc    = fminf(fmaxf(dv, -1.f), 1.f);
                gd                 = gating * dvc;
                s_new              = s + (gd - s) / 10.0f;         // TAU_S
                spk                = (v_next >=  1.f) ? 1.f : 0.f;
                const float sn     = (v_next <= -1.f) ? 1.f : 0.f;
                v_new              = (1.f + spk - sn) * v_next;    // matches reference exactly

                v = v_new; s = s_new;
                __stcg(&g_state[wb][j], make_float2(s_new, gd));
            }
            // publish progress FIRST (release orders the state stores above)
            if (lane == 0) red_release_add(&g_cnt[t + 1], 1u);

            // non-critical outputs after the release
            if (active) {
                out_spikes[(size_t)t * NN + j] = spk;
                out_vs[(size_t)t * NN + j]     = v_new;
                r0 = o0 * s_new;
                r1 = o1 * s_new;
            }
            #pragma unroll
            for (int o = 16; o; o >>= 1) {
                r0 += __shfl_down_sync(0xffffffffu, r0, o);
                r1 += __shfl_down_sync(0xffffffffu, r1, o);
            }
            if (lane == 0) {
                g_part[((size_t)t * G + b) * 2 + 0] = r0;
                g_part[((size_t)t * G + b) * 2 + 1] = r1;
            }
        }
    }

    // bump the epoch slot (one per CTA per replay)
    if (warp == 0 && lane == 0) red_release_add(&g_cnt[TT + 1], 1u);
}

// epilogue: one warp per timestep, coalesced float2 loads + shfl reduce
__global__ void readout_kernel(float* __restrict__ out_ro) {
    const int t    = blockIdx.x * (blockDim.x >> 5) + (threadIdx.x >> 5);
    const int lane = threadIdx.x & 31;
    if (t < TT) {
        const float2* p = reinterpret_cast<const float2*>(&g_part[(size_t)t * G * 2]);
        float a = 0.f, c = 0.f;
        for (int bb = lane; bb < G; bb += 32) {
            const float2 pv = p[bb];
            a += pv.x;
            c += pv.y;
        }
        #pragma unroll
        for (int o = 16; o; o >>= 1) {
            a += __shfl_down_sync(0xffffffffu, a, o);
            c += __shfl_down_sync(0xffffffffu, c, o);
        }
        if (lane == 0) {
            out_ro[2 * t]     = a;
            out_ro[2 * t + 1] = c;
        }
    }
}

extern "C" void kernel_launch(void* const* d_in, const int* in_sizes, int n_in,
                              void* d_out, int out_size) {
    const float* x_in   = (const float*)d_in[0];
    const float* W_syn  = (const float*)d_in[1];
    const float* W_fast = (const float*)d_in[2];
    const float* W_in   = (const float*)d_in[3];
    const float* I_o    = (const float*)d_in[4];
    const float* O      = (const float*)d_in[5];

    float* out        = (float*)d_out;
    float* out_spikes = out;                                // [T][N]
    float* out_ro     = out + (size_t)TT * NN;              // [T][2]
    float* out_vs     = out + (size_t)TT * NN + 2 * TT;     // [T][N]

    cudaFuncSetAttribute(nlif_kernel,
                         cudaFuncAttributeMaxDynamicSharedMemorySize, SMEM_BYTES);

    nlif_kernel<<<G, NTHREADS, SMEM_BYTES>>>(x_in, W_syn, W_fast, W_in, I_o, O,
                                             out_spikes, out_vs);
    // 8 warps per block, one warp per timestep
    readout_kernel<<<TT / 8, NTHREADS>>>(out_ro);
}

// round 10
// speedup vs baseline: 1.7671x; 1.1021x over previous
#include <cuda_runtime.h>

// ---------------------------------------------------------------------------
// NLIF recurrent spiking net — persistent kernel.
// Round 10: R9 core + butterfly multi-column reduce (70 -> 16 SHFL/warp).
// Single-variable test of the reduce (R8 bundled it with two regressions).
// ---------------------------------------------------------------------------

#define NN 2048
#define TT 2048
#define G  147           // CTAs, 1 per SM (all co-resident on 148 SMs)
#define CPT 14           // columns per CTA (147*14 = 2058 >= 2048)
#define NTHREADS 256
#define NWARPS 8
#define CSTRF 4096       // floats per column slab: 2048 rows x (ws,wf)

#define SMEM_BYTES ((CPT * CSTRF + 16 * NWARPS) * 4)

// persistent device state (no allocations allowed)
__device__ __align__(16) float2 g_state[2][NN];   // (s, s_fast), double-buffered
__device__ unsigned g_cnt[TT + 2];                // per-step counters + epoch slot
__device__ float g_part[TT * G * 2];              // per-CTA readout partials

__device__ __forceinline__ unsigned ld_relaxed_u32(const unsigned* p) {
    unsigned v;
    asm volatile("ld.relaxed.gpu.global.u32 %0, [%1];" : "=r"(v) : "l"(p) : "memory");
    return v;
}
__device__ __forceinline__ void red_release_add(unsigned* p, unsigned v) {
    asm volatile("red.release.gpu.global.add.u32 [%0], %1;" :: "l"(p), "r"(v) : "memory");
}

__global__ void __launch_bounds__(NTHREADS, 1)
nlif_kernel(const float* __restrict__ x_in,    // [T][2]
            const float* __restrict__ W_syn,   // [N][N]
            const float* __restrict__ W_fast,  // [N][N]
            const float* __restrict__ W_in,    // [2][N]
            const float* __restrict__ I_o,     // [N]
            const float* __restrict__ O,       // [2][N]
            float* __restrict__ out_spikes,    // [T][N]
            float* __restrict__ out_vs)        // [T][N]
{
    extern __shared__ float smem[];
    float* Wc  = smem;                    // [CPT][CSTRF] : per pair p, (ws0,wf0,ws1,wf1)
    float* red = smem + CPT * CSTRF;      // [16][NWARPS]

    const int tid  = threadIdx.x;
    const int warp = tid >> 5;
    const int lane = tid & 31;
    const int b    = blockIdx.x;
    const int j0   = b * CPT;

    // epoch base: all counters equal R*G at launch start; slot TT+1 is bumped
    // once per CTA at kernel end, so it reads exactly R*G here.
    const unsigned base = ld_relaxed_u32(&g_cnt[TT + 1]);
    const unsigned tgt0 = base + (unsigned)G;

    // ---- stage weight columns into SMEM, interleaved (ws,wf) per row ----
    for (int i = warp; i < NN; i += NWARPS) {
        if (lane < CPT) {
            const int jj = j0 + lane;
            float ws = 0.f, wf = 0.f;
            if (jj < NN) {
                ws = W_syn[(size_t)i * NN + jj];
                wf = W_fast[(size_t)i * NN + jj];
                if (i == jj) ws = 0.f;              // self-recurrence mask
            }
            const int p = i >> 1, r = i & 1;
            Wc[lane * CSTRF + p * 4 + r * 2 + 0] = ws;
            Wc[lane * CSTRF + p * 4 + r * 2 + 1] = wf;
        }
    }
    __syncthreads();

    // ---- pull k=1,2,3 weight chunks into registers (168 regs/thread) ----
    float4 wr[CPT][3];
    #pragma unroll
    for (int c = 0; c < CPT; c++) {
        #pragma unroll
        for (int kk = 0; kk < 3; kk++) {
            const int p = (kk + 1) * NTHREADS + tid;
            wr[c][kk] = *reinterpret_cast<const float4*>(&Wc[c * CSTRF + p * 4]);
        }
    }

    // ---- per-column persistent state in warp-0 registers ----
    const int j = j0 + lane;
    const bool active = (warp == 0) && (lane < CPT) && (j < NN);
    float v = 0.f, s = 0.f;
    float wi0 = 0.f, wi1 = 0.f, io = 0.f, o0 = 0.f, o1 = 0.f;
    if (active) {
        wi0 = W_in[j];
        wi1 = W_in[NN + j];
        io  = I_o[j];
        o0  = O[j];
        o1  = O[NN + j];
        __stcg(&g_state[0][j], make_float2(0.f, 0.f));   // t=0 reads parity-0 zeros
    }
    if (warp == 0 && lane == 0) red_release_add(&g_cnt[0], 1u);  // initial publish

    for (int t = 0; t < TT; t++) {
        const int rb = t & 1;
        const int wb = rb ^ 1;

        float x0 = 0.f, x1 = 0.f;
        if (warp == 0) {
            x0 = __ldg(&x_in[2 * t]);            // prefetch input before the wait
            x1 = __ldg(&x_in[2 * t + 1]);
            // relaxed hot-spin (no separate acquire; see R9 rationale)
            const unsigned* cp = &g_cnt[t];
            unsigned f = ld_relaxed_u32(cp);
            while ((int)(f - tgt0) < 0) {
                f = ld_relaxed_u32(cp);
            }
        }
        __syncthreads();

        // ---- load state: 4 coalesced float4 (rows 2p, 2p+1 per float4) ----
        const float2* srow = g_state[rb];
        float4 st[4];
        #pragma unroll
        for (int k = 0; k < 4; k++) {
            const int p = k * NTHREADS + tid;
            st[k] = __ldcg(reinterpret_cast<const float4*>(&srow[2 * p]));
        }

        // ---- dot products: k=0 from SMEM (conflict-free LDS.128), k=1,2,3 from regs ----
        float acc[16];
        #pragma unroll
        for (int c = 0; c < CPT; c++) {
            float a = 0.f;
            {
                const float4 w = *reinterpret_cast<const float4*>(&Wc[c * CSTRF + tid * 4]);
                a = fmaf(st[0].x, w.x, a);
                a = fmaf(st[0].y, w.y, a);
                a = fmaf(st[0].z, w.z, a);
                a = fmaf(st[0].w, w.w, a);
            }
            #pragma unroll
            for (int kk = 0; kk < 3; kk++) {
                const float4 w = wr[c][kk];
                const float4 sv = st[kk + 1];
                a = fmaf(sv.x, w.x, a);
                a = fmaf(sv.y, w.y, a);
                a = fmaf(sv.z, w.z, a);
                a = fmaf(sv.w, w.w, a);
            }
            acc[c] = a;
        }
        acc[14] = 0.f;
        acc[15] = 0.f;

        // ---- butterfly multi-column reduce: 16 SHFL + 16 FADD per warp ----
        // After all levels, lanes 2c and 2c+1 hold the warp sum of column c.
        #pragma unroll
        for (int i = 0; i < 8; i++) {
            const float give = (lane & 16) ? acc[i] : acc[i + 8];
            const float got  = __shfl_xor_sync(0xffffffffu, give, 16);
            const float keep = (lane & 16) ? acc[i + 8] : acc[i];
            acc[i] = keep + got;
        }
        #pragma unroll
        for (int i = 0; i < 4; i++) {
            const float give = (lane & 8) ? acc[i] : acc[i + 4];
            const float got  = __shfl_xor_sync(0xffffffffu, give, 8);
            const float keep = (lane & 8) ? acc[i + 4] : acc[i];
            acc[i] = keep + got;
        }
        #pragma unroll
        for (int i = 0; i < 2; i++) {
            const float give = (lane & 4) ? acc[i] : acc[i + 2];
            const float got  = __shfl_xor_sync(0xffffffffu, give, 4);
            const float keep = (lane & 4) ? acc[i + 2] : acc[i];
            acc[i] = keep + got;
        }
        {
            const float give = (lane & 2) ? acc[0] : acc[1];
            const float got  = __shfl_xor_sync(0xffffffffu, give, 2);
            const float keep = (lane & 2) ? acc[1] : acc[0];
            acc[0] = keep + got;
        }
        acc[0] += __shfl_xor_sync(0xffffffffu, acc[0], 1);

        if ((lane & 1) == 0) red[((lane >> 1) & 15) * NWARPS + warp] = acc[0];
        __syncthreads();

        if (warp == 0) {
            float r0 = 0.f, r1 = 0.f;
            float s_new = 0.f, gd = 0.f, spk = 0.f, v_new = 0.f;
            if (active) {
                const float4 p0 = *reinterpret_cast<const float4*>(&red[lane * NWARPS]);
                const float4 p1 = *reinterpret_cast<const float4*>(&red[lane * NWARPS + 4]);
                const float sum = ((p0.x + p0.y) + (p0.z + p0.w)) +
                                  ((p1.x + p1.y) + (p1.z + p1.w));

                const float I_tot  = sum + x0 * wi0 + x1 * wi1 + io;
                const float dv     = (I_tot - v) / 10.0f;          // TAU_M
                const float v_next = v + dv;
                const float gating = fminf(fmaxf(v_next, -1.f), 1.f);
                const float dvc    = fminf(fmaxf(dv, -1.f), 1.f);
                gd                 = gating * dvc;
                s_new              = s + (gd - s) / 10.0f;         // TAU_S
                spk                = (v_next >=  1.f) ? 1.f : 0.f;
                const float sn     = (v_next <= -1.f) ? 1.f : 0.f;
                v_new              = (1.f + spk - sn) * v_next;    // matches reference exactly

                v = v_new; s = s_new;
                __stcg(&g_state[wb][j], make_float2(s_new, gd));
            }
            // publish progress FIRST (release orders the state stores above)
            if (lane == 0) red_release_add(&g_cnt[t + 1], 1u);

            // non-critical outputs after the release
            if (active) {
                out_spikes[(size_t)t * NN + j] = spk;
                out_vs[(size_t)t * NN + j]     = v_new;
                r0 = o0 * s_new;
                r1 = o1 * s_new;
            }
            #pragma unroll
            for (int o = 16; o; o >>= 1) {
                r0 += __shfl_down_sync(0xffffffffu, r0, o);
                r1 += __shfl_down_sync(0xffffffffu, r1, o);
            }
            if (lane == 0) {
                g_part[((size_t)t * G + b) * 2 + 0] = r0;
                g_part[((size_t)t * G + b) * 2 + 1] = r1;
            }
        }
    }

    // bump the epoch slot (one per CTA per replay)
    if (warp == 0 && lane == 0) red_release_add(&g_cnt[TT + 1], 1u);
}

// epilogue: one warp per timestep, coalesced float2 loads + shfl reduce
__global__ void readout_kernel(float* __restrict__ out_ro) {
    const int t    = blockIdx.x * (blockDim.x >> 5) + (threadIdx.x >> 5);
    const int lane = threadIdx.x & 31;
    if (t < TT) {
        const float2* p = reinterpret_cast<const float2*>(&g_part[(size_t)t * G * 2]);
        float a = 0.f, c = 0.f;
        for (int bb = lane; bb < G; bb += 32) {
            const float2 pv = p[bb];
            a += pv.x;
            c += pv.y;
        }
        #pragma unroll
        for (int o = 16; o; o >>= 1) {
            a += __shfl_down_sync(0xffffffffu, a, o);
            c += __shfl_down_sync(0xffffffffu, c, o);
        }
        if (lane == 0) {
            out_ro[2 * t]     = a;
            out_ro[2 * t + 1] = c;
        }
    }
}

extern "C" void kernel_launch(void* const* d_in, const int* in_sizes, int n_in,
                              void* d_out, int out_size) {
    const float* x_in   = (const float*)d_in[0];
    const float* W_syn  = (const float*)d_in[1];
    const float* W_fast = (const float*)d_in[2];
    const float* W_in   = (const float*)d_in[3];
    const float* I_o    = (const float*)d_in[4];
    const float* O      = (const float*)d_in[5];

    float* out        = (float*)d_out;
    float* out_spikes = out;                                // [T][N]
    float* out_ro     = out + (size_t)TT * NN;              // [T][2]
    float* out_vs     = out + (size_t)TT * NN + 2 * TT;     // [T][N]

    cudaFuncSetAttribute(nlif_kernel,
                         cudaFuncAttributeMaxDynamicSharedMemorySize, SMEM_BYTES);

    nlif_kernel<<<G, NTHREADS, SMEM_BYTES>>>(x_in, W_syn, W_fast, W_in, I_o, O,
                                             out_spikes, out_vs);
    // 8 warps per block, one warp per timestep
    readout_kernel<<<TT / 8, NTHREADS>>>(out_ro);
}

// round 11
// speedup vs baseline: 1.7677x; 1.0004x over previous
#include <cuda_runtime.h>

// ---------------------------------------------------------------------------
// NLIF recurrent spiking net — persistent kernel.
// Round 11: R10 + chunk-major FMA ordering (single variable). First 56 FMAs
// depend only on st[0], hiding the 2.35MB/step L2 state-load burst under the
// FFMA issue floor. Per-accumulator FP order unchanged -> bit-identical.
// ---------------------------------------------------------------------------

#define NN 2048
#define TT 2048
#define G  147           // CTAs, 1 per SM (all co-resident on 148 SMs)
#define CPT 14           // columns per CTA (147*14 = 2058 >= 2048)
#define NTHREADS 256
#define NWARPS 8
#define CSTRF 4096       // floats per column slab: 2048 rows x (ws,wf)

#define SMEM_BYTES ((CPT * CSTRF + 16 * NWARPS) * 4)

// persistent device state (no allocations allowed)
__device__ __align__(16) float2 g_state[2][NN];   // (s, s_fast), double-buffered
__device__ unsigned g_cnt[TT + 2];                // per-step counters + epoch slot
__device__ float g_part[TT * G * 2];              // per-CTA readout partials

__device__ __forceinline__ unsigned ld_relaxed_u32(const unsigned* p) {
    unsigned v;
    asm volatile("ld.relaxed.gpu.global.u32 %0, [%1];" : "=r"(v) : "l"(p) : "memory");
    return v;
}
__device__ __forceinline__ void red_release_add(unsigned* p, unsigned v) {
    asm volatile("red.release.gpu.global.add.u32 [%0], %1;" :: "l"(p), "r"(v) : "memory");
}

__global__ void __launch_bounds__(NTHREADS, 1)
nlif_kernel(const float* __restrict__ x_in,    // [T][2]
            const float* __restrict__ W_syn,   // [N][N]
            const float* __restrict__ W_fast,  // [N][N]
            const float* __restrict__ W_in,    // [2][N]
            const float* __restrict__ I_o,     // [N]
            const float* __restrict__ O,       // [2][N]
            float* __restrict__ out_spikes,    // [T][N]
            float* __restrict__ out_vs)        // [T][N]
{
    extern __shared__ float smem[];
    float* Wc  = smem;                    // [CPT][CSTRF] : per pair p, (ws0,wf0,ws1,wf1)
    float* red = smem + CPT * CSTRF;      // [16][NWARPS]

    const int tid  = threadIdx.x;
    const int warp = tid >> 5;
    const int lane = tid & 31;
    const int b    = blockIdx.x;
    const int j0   = b * CPT;

    // epoch base: all counters equal R*G at launch start; slot TT+1 is bumped
    // once per CTA at kernel end, so it reads exactly R*G here.
    const unsigned base = ld_relaxed_u32(&g_cnt[TT + 1]);
    const unsigned tgt0 = base + (unsigned)G;

    // ---- stage weight columns into SMEM, interleaved (ws,wf) per row ----
    for (int i = warp; i < NN; i += NWARPS) {
        if (lane < CPT) {
            const int jj = j0 + lane;
            float ws = 0.f, wf = 0.f;
            if (jj < NN) {
                ws = W_syn[(size_t)i * NN + jj];
                wf = W_fast[(size_t)i * NN + jj];
                if (i == jj) ws = 0.f;              // self-recurrence mask
            }
            const int p = i >> 1, r = i & 1;
            Wc[lane * CSTRF + p * 4 + r * 2 + 0] = ws;
            Wc[lane * CSTRF + p * 4 + r * 2 + 1] = wf;
        }
    }
    __syncthreads();

    // ---- pull k=1,2,3 weight chunks into registers (168 regs/thread) ----
    float4 wr[CPT][3];
    #pragma unroll
    for (int c = 0; c < CPT; c++) {
        #pragma unroll
        for (int kk = 0; kk < 3; kk++) {
            const int p = (kk + 1) * NTHREADS + tid;
            wr[c][kk] = *reinterpret_cast<const float4*>(&Wc[c * CSTRF + p * 4]);
        }
    }

    // ---- per-column persistent state in warp-0 registers ----
    const int j = j0 + lane;
    const bool active = (warp == 0) && (lane < CPT) && (j < NN);
    float v = 0.f, s = 0.f;
    float wi0 = 0.f, wi1 = 0.f, io = 0.f, o0 = 0.f, o1 = 0.f;
    if (active) {
        wi0 = W_in[j];
        wi1 = W_in[NN + j];
        io  = I_o[j];
        o0  = O[j];
        o1  = O[NN + j];
        __stcg(&g_state[0][j], make_float2(0.f, 0.f));   // t=0 reads parity-0 zeros
    }
    if (warp == 0 && lane == 0) red_release_add(&g_cnt[0], 1u);  // initial publish

    for (int t = 0; t < TT; t++) {
        const int rb = t & 1;
        const int wb = rb ^ 1;

        float x0 = 0.f, x1 = 0.f;
        if (warp == 0) {
            x0 = __ldg(&x_in[2 * t]);            // prefetch input before the wait
            x1 = __ldg(&x_in[2 * t + 1]);
            // relaxed hot-spin (no separate acquire; see R9 rationale)
            const unsigned* cp = &g_cnt[t];
            unsigned f = ld_relaxed_u32(cp);
            while ((int)(f - tgt0) < 0) {
                f = ld_relaxed_u32(cp);
            }
        }
        __syncthreads();

        // ---- load state: 4 coalesced float4 (rows 2p, 2p+1 per float4) ----
        const float2* srow = g_state[rb];
        float4 st[4];
        #pragma unroll
        for (int k = 0; k < 4; k++) {
            const int p = k * NTHREADS + tid;
            st[k] = __ldcg(reinterpret_cast<const float4*>(&srow[2 * p]));
        }

        // ---- dot products, CHUNK-MAJOR: the first 14x4 FMAs depend only on
        //      st[0]; k=1..3 blocks only on their own chunk. Per-accumulator
        //      FP order is unchanged (k ascending, x->y->z->w): bit-identical.
        float acc[16];
        #pragma unroll
        for (int c = 0; c < CPT; c++) {
            const float4 w = *reinterpret_cast<const float4*>(&Wc[c * CSTRF + tid * 4]);
            float a = 0.f;
            a = fmaf(st[0].x, w.x, a);
            a = fmaf(st[0].y, w.y, a);
            a = fmaf(st[0].z, w.z, a);
            a = fmaf(st[0].w, w.w, a);
            acc[c] = a;
        }
        #pragma unroll
        for (int kk = 0; kk < 3; kk++) {
            const float4 sv = st[kk + 1];
            #pragma unroll
            for (int c = 0; c < CPT; c++) {
                const float4 w = wr[c][kk];
                float a = acc[c];
                a = fmaf(sv.x, w.x, a);
                a = fmaf(sv.y, w.y, a);
                a = fmaf(sv.z, w.z, a);
                a = fmaf(sv.w, w.w, a);
                acc[c] = a;
            }
        }
        acc[14] = 0.f;
        acc[15] = 0.f;

        // ---- butterfly multi-column reduce: 16 SHFL + 16 FADD per warp ----
        #pragma unroll
        for (int i = 0; i < 8; i++) {
            const float give = (lane & 16) ? acc[i] : acc[i + 8];
            const float got  = __shfl_xor_sync(0xffffffffu, give, 16);
            const float keep = (lane & 16) ? acc[i + 8] : acc[i];
            acc[i] = keep + got;
        }
        #pragma unroll
        for (int i = 0; i < 4; i++) {
            const float give = (lane & 8) ? acc[i] : acc[i + 4];
            const float got  = __shfl_xor_sync(0xffffffffu, give, 8);
            const float keep = (lane & 8) ? acc[i + 4] : acc[i];
            acc[i] = keep + got;
        }
        #pragma unroll
        for (int i = 0; i < 2; i++) {
            const float give = (lane & 4) ? acc[i] : acc[i + 2];
            const float got  = __shfl_xor_sync(0xffffffffu, give, 4);
            const float keep = (lane & 4) ? acc[i + 2] : acc[i];
            acc[i] = keep + got;
        }
        {
            const float give = (lane & 2) ? acc[0] : acc[1];
            const float got  = __shfl_xor_sync(0xffffffffu, give, 2);
            const float keep = (lane & 2) ? acc[1] : acc[0];
            acc[0] = keep + got;
        }
        acc[0] += __shfl_xor_sync(0xffffffffu, acc[0], 1);

        if ((lane & 1) == 0) red[((lane >> 1) & 15) * NWARPS + warp] = acc[0];
        __syncthreads();

        if (warp == 0) {
            float r0 = 0.f, r1 = 0.f;
            float s_new = 0.f, gd = 0.f, spk = 0.f, v_new = 0.f;
            if (active) {
                const float4 p0 = *reinterpret_cast<const float4*>(&red[lane * NWARPS]);
                const float4 p1 = *reinterpret_cast<const float4*>(&red[lane * NWARPS + 4]);
                const float sum = ((p0.x + p0.y) + (p0.z + p0.w)) +
                                  ((p1.x + p1.y) + (p1.z + p1.w));

                const float I_tot  = sum + x0 * wi0 + x1 * wi1 + io;
                const float dv     = (I_tot - v) / 10.0f;          // TAU_M
                const float v_next = v + dv;
                const float gating = fminf(fmaxf(v_next, -1.f), 1.f);
                const float dvc    = fminf(fmaxf(dv, -1.f), 1.f);
                gd                 = gating * dvc;
                s_new              = s + (gd - s) / 10.0f;         // TAU_S
                spk                = (v_next >=  1.f) ? 1.f : 0.f;
                const float sn     = (v_next <= -1.f) ? 1.f : 0.f;
                v_new              = (1.f + spk - sn) * v_next;    // matches reference exactly

                v = v_new; s = s_new;
                __stcg(&g_state[wb][j], make_float2(s_new, gd));
            }
            // publish progress FIRST (release orders the state stores above)
            if (lane == 0) red_release_add(&g_cnt[t + 1], 1u);

            // non-critical outputs after the release
            if (active) {
                out_spikes[(size_t)t * NN + j] = spk;
                out_vs[(size_t)t * NN + j]     = v_new;
                r0 = o0 * s_new;
                r1 = o1 * s_new;
            }
            #pragma unroll
            for (int o = 16; o; o >>= 1) {
                r0 += __shfl_down_sync(0xffffffffu, r0, o);
                r1 += __shfl_down_sync(0xffffffffu, r1, o);
            }
            if (lane == 0) {
                g_part[((size_t)t * G + b) * 2 + 0] = r0;
                g_part[((size_t)t * G + b) * 2 + 1] = r1;
            }
        }
    }

    // bump the epoch slot (one per CTA per replay)
    if (warp == 0 && lane == 0) red_release_add(&g_cnt[TT + 1], 1u);
}

// epilogue: one warp per timestep, coalesced float2 loads + shfl reduce
__global__ void readout_kernel(float* __restrict__ out_ro) {
    const int t    = blockIdx.x * (blockDim.x >> 5) + (threadIdx.x >> 5);
    const int lane = threadIdx.x & 31;
    if (t < TT) {
        const float2* p = reinterpret_cast<const float2*>(&g_part[(size_t)t * G * 2]);
        float a = 0.f, c = 0.f;
        for (int bb = lane; bb < G; bb += 32) {
            const float2 pv = p[bb];
            a += pv.x;
            c += pv.y;
        }
        #pragma unroll
        for (int o = 16; o; o >>= 1) {
            a += __shfl_down_sync(0xffffffffu, a, o);
            c += __shfl_down_sync(0xffffffffu, c, o);
        }
        if (lane == 0) {
            out_ro[2 * t]     = a;
            out_ro[2 * t + 1] = c;
        }
    }
}

extern "C" void kernel_launch(void* const* d_in, const int* in_sizes, int n_in,
                              void* d_out, int out_size) {
    const float* x_in   = (const float*)d_in[0];
    const float* W_syn  = (const float*)d_in[1];
    const float* W_fast = (const float*)d_in[2];
    const float* W_in   = (const float*)d_in[3];
    const float* I_o    = (const float*)d_in[4];
    const float* O      = (const float*)d_in[5];

    float* out        = (float*)d_out;
    float* out_spikes = out;                                // [T][N]
    float* out_ro     = out + (size_t)TT * NN;              // [T][2]
    float* out_vs     = out + (size_t)TT * NN + 2 * TT;     // [T][N]

    cudaFuncSetAttribute(nlif_kernel,
                         cudaFuncAttributeMaxDynamicSharedMemorySize, SMEM_BYTES);

    nlif_kernel<<<G, NTHREADS, SMEM_BYTES>>>(x_in, W_syn, W_fast, W_in, I_o, O,
                                             out_spikes, out_vs);
    // 8 warps per block, one warp per timestep
    readout_kernel<<<TT / 8, NTHREADS>>>(out_ro);
}